// round 1
// baseline (speedup 1.0000x reference)
#include <cuda_runtime.h>
#include <cstdint>

#define MUL 64
#define NODE_TILE 64
#define THREADS 256
#define GRID_CTAS 148

// constants
#define ALPHA_C   0.08838834764831845f   /* 1/sqrt(128) */
#define C110_C    0.5773502691896258f    /* 1/sqrt(3) */
#define C011_C    0.5773502691896258f
#define C101_C    0.5773502691896258f

// smem layout (floats)
#define STRIDE_B1 132
#define STRIDE_W  68
#define STRIDE_A1 132
#define STRIDE_A2 68

#define OFF_B1   0                         // 128 x 132
#define OFF_W3   (OFF_B1 + 128*STRIDE_B1)  // 64 x 68
#define OFF_W4   (OFF_W3 + 64*STRIDE_W)    // 64 x 68
#define OFF_A1   (OFF_W4 + 64*STRIDE_W)    // 64 x 132   (reused for SG result)
#define OFF_A2   (OFF_A1 + 64*STRIDE_A1)   // 256 x 68   (reused for V/Z result)
#define OFF_ATTR (OFF_A2 + 256*STRIDE_A2)  // 64 x 4
#define SMEM_FLOATS (OFF_ATTR + 64*4)
#define SMEM_BYTES (SMEM_FLOATS * 4)

__device__ __forceinline__ float to_tf32(float x) {
    uint32_t u;
    asm("cvt.rna.tf32.f32 %0, %1;" : "=r"(u) : "f"(x));
    return __uint_as_float(u);
}

__device__ __forceinline__ void mma_tf32(float c[4],
                                         uint32_t a0, uint32_t a1, uint32_t a2, uint32_t a3,
                                         uint32_t b0, uint32_t b1) {
    asm volatile(
        "mma.sync.aligned.m16n8k8.row.col.f32.tf32.tf32.f32 "
        "{%0,%1,%2,%3}, {%4,%5,%6,%7}, {%8,%9}, {%0,%1,%2,%3};"
        : "+f"(c[0]), "+f"(c[1]), "+f"(c[2]), "+f"(c[3])
        : "r"(a0), "r"(a1), "r"(a2), "r"(a3), "r"(b0), "r"(b1));
}

__global__ void __launch_bounds__(THREADS, 1)
embedding_kernel(const float* __restrict__ feats,
                 const float* __restrict__ attrs,
                 const float* __restrict__ W1,
                 const float* __restrict__ W2,
                 const float* __restrict__ W3,
                 const float* __restrict__ W4,
                 float* __restrict__ out,
                 int n, int ntiles)
{
    extern __shared__ float sm[];
    float* sB1 = sm + OFF_B1;
    float* sW3 = sm + OFF_W3;
    float* sW4 = sm + OFF_W4;
    float* sA1 = sm + OFF_A1;   // [64][132] : A1 input, then SG result
    float* sA2 = sm + OFF_A2;   // [256][68] : [X0;X1c] input, then [V;Z] result
    float* sAttr = sm + OFF_ATTR;

    const int tid = threadIdx.x;
    const int lane = tid & 31;
    const int warp = tid >> 5;
    const int g = lane >> 2;       // 0..7
    const int tig = lane & 3;      // 0..3

    // ---- load + convert weights once per CTA ----
    for (int idx = tid; idx < 128 * 128; idx += THREADS) {
        int k = idx >> 7, nn = idx & 127;
        float v = (k < 64) ? W1[k * 128 + nn] : W2[(k - 64) * 128 + nn];
        sB1[k * STRIDE_B1 + nn] = to_tf32(v);
    }
    for (int idx = tid; idx < 64 * 64; idx += THREADS) {
        int r = idx >> 6, c = idx & 63;
        sW3[r * STRIDE_W + c] = to_tf32(W3[idx]);
        sW4[r * STRIDE_W + c] = to_tf32(W4[idx]);
    }

    // persistent tile loop
    for (int tile = blockIdx.x; tile < ntiles; tile += gridDim.x) {
        const int nb = tile * NODE_TILE;

        __syncthreads();   // previous epilogue fully done before restaging

        // ---- stage node data: build A1 = [a0*x0 | C110*(x1 . a1)], A2 = [x0; x1_0; x1_1; x1_2] ----
        {
            const int z = tid >> 2;        // node within tile: 0..63
            const int q = tid & 3;         // quarter: 16 u-values each
            const int zg = nb + z;
            const bool valid = (zg < n);

            float4 at4 = valid ? ((const float4*)attrs)[zg] : make_float4(0.f, 0.f, 0.f, 0.f);
            if (q == 0) ((float4*)sAttr)[z] = at4;
            const float a0v = at4.x, a1x = at4.y, a1y = at4.z, a1z = at4.w;

            const float* fr = feats + (size_t)zg * (4 * MUL);

            // x0 quarter: u in [16q, 16q+16)
            #pragma unroll
            for (int j = 0; j < 4; j++) {
                float4 f = valid ? ((const float4*)fr)[q * 4 + j] : make_float4(0.f, 0.f, 0.f, 0.f);
                int u = q * 16 + j * 4;
                sA2[z * STRIDE_A2 + u + 0] = to_tf32(f.x);
                sA2[z * STRIDE_A2 + u + 1] = to_tf32(f.y);
                sA2[z * STRIDE_A2 + u + 2] = to_tf32(f.z);
                sA2[z * STRIDE_A2 + u + 3] = to_tf32(f.w);
                sA1[z * STRIDE_A1 + u + 0] = to_tf32(a0v * f.x);
                sA1[z * STRIDE_A1 + u + 1] = to_tf32(a0v * f.y);
                sA1[z * STRIDE_A1 + u + 2] = to_tf32(a0v * f.z);
                sA1[z * STRIDE_A1 + u + 3] = to_tf32(a0v * f.w);
            }

            // x1 quarter: 48 floats = feats[64 + 48q .. +47]
            float vb[48];
            #pragma unroll
            for (int j = 0; j < 12; j++) {
                float4 f = valid ? ((const float4*)(fr + 64))[q * 12 + j]
                                 : make_float4(0.f, 0.f, 0.f, 0.f);
                vb[4 * j + 0] = f.x; vb[4 * j + 1] = f.y;
                vb[4 * j + 2] = f.z; vb[4 * j + 3] = f.w;
            }
            #pragma unroll
            for (int uu = 0; uu < 16; uu++) {
                int u = q * 16 + uu;
                float c0 = vb[3 * uu + 0], c1 = vb[3 * uu + 1], c2 = vb[3 * uu + 2];
                sA1[z * STRIDE_A1 + 64 + u] =
                    to_tf32(C110_C * (a1x * c0 + a1y * c1 + a1z * c2));
                sA2[(64 + z)   * STRIDE_A2 + u] = to_tf32(c0);
                sA2[(128 + z)  * STRIDE_A2 + u] = to_tf32(c1);
                sA2[(192 + z)  * STRIDE_A2 + u] = to_tf32(c2);
            }
        }
        __syncthreads();

        // ---- phase 1: SG(64x128) = A1(64x128) @ B1(128x128) ----
        {
            const int m0 = (warp & 3) * 16;
            const int n0 = (warp >> 2) * 64;
            float c[8][4];
            #pragma unroll
            for (int nt = 0; nt < 8; nt++)
                #pragma unroll
                for (int i = 0; i < 4; i++) c[nt][i] = 0.f;

            #pragma unroll
            for (int ks = 0; ks < 16; ks++) {
                const int k = ks * 8;
                uint32_t a0 = __float_as_uint(sA1[(m0 + g)     * STRIDE_A1 + k + tig]);
                uint32_t a1 = __float_as_uint(sA1[(m0 + g + 8) * STRIDE_A1 + k + tig]);
                uint32_t a2 = __float_as_uint(sA1[(m0 + g)     * STRIDE_A1 + k + tig + 4]);
                uint32_t a3 = __float_as_uint(sA1[(m0 + g + 8) * STRIDE_A1 + k + tig + 4]);
                #pragma unroll
                for (int nt = 0; nt < 8; nt++) {
                    const int nn = n0 + nt * 8;
                    uint32_t b0 = __float_as_uint(sB1[(k + tig)     * STRIDE_B1 + nn + g]);
                    uint32_t b1 = __float_as_uint(sB1[(k + tig + 4) * STRIDE_B1 + nn + g]);
                    mma_tf32(c[nt], a0, a1, a2, a3, b0, b1);
                }
            }
            __syncthreads();   // all phase-1 reads of sA1 done
            #pragma unroll
            for (int nt = 0; nt < 8; nt++) {
                const int nn = n0 + nt * 8;
                sA1[(m0 + g)     * STRIDE_A1 + nn + 2 * tig]     = c[nt][0];
                sA1[(m0 + g)     * STRIDE_A1 + nn + 2 * tig + 1] = c[nt][1];
                sA1[(m0 + g + 8) * STRIDE_A1 + nn + 2 * tig]     = c[nt][2];
                sA1[(m0 + g + 8) * STRIDE_A1 + nn + 2 * tig + 1] = c[nt][3];
            }
        }

        // ---- phase 2: [V;Z](256x64) = [X0;X1c](256x64) @ (W3 for rows<64 else W4) ----
        {
            const int m0 = warp * 32;
            const float* Wm = (warp < 2) ? sW3 : sW4;
            float c[2][8][4];
            #pragma unroll
            for (int mb = 0; mb < 2; mb++)
                #pragma unroll
                for (int nt = 0; nt < 8; nt++)
                    #pragma unroll
                    for (int i = 0; i < 4; i++) c[mb][nt][i] = 0.f;

            #pragma unroll
            for (int ks = 0; ks < 8; ks++) {
                const int k = ks * 8;
                uint32_t a[2][4];
                #pragma unroll
                for (int mb = 0; mb < 2; mb++) {
                    const int r = m0 + mb * 16;
                    a[mb][0] = __float_as_uint(sA2[(r + g)     * STRIDE_A2 + k + tig]);
                    a[mb][1] = __float_as_uint(sA2[(r + g + 8) * STRIDE_A2 + k + tig]);
                    a[mb][2] = __float_as_uint(sA2[(r + g)     * STRIDE_A2 + k + tig + 4]);
                    a[mb][3] = __float_as_uint(sA2[(r + g + 8) * STRIDE_A2 + k + tig + 4]);
                }
                #pragma unroll
                for (int nt = 0; nt < 8; nt++) {
                    const int nn = nt * 8;
                    uint32_t b0 = __float_as_uint(Wm[(k + tig)     * STRIDE_W + nn + g]);
                    uint32_t b1 = __float_as_uint(Wm[(k + tig + 4) * STRIDE_W + nn + g]);
                    mma_tf32(c[0][nt], a[0][0], a[0][1], a[0][2], a[0][3], b0, b1);
                    mma_tf32(c[1][nt], a[1][0], a[1][1], a[1][2], a[1][3], b0, b1);
                }
            }
            __syncthreads();   // all phase-2 reads of sA2 done
            #pragma unroll
            for (int mb = 0; mb < 2; mb++) {
                const int r = m0 + mb * 16;
                #pragma unroll
                for (int nt = 0; nt < 8; nt++) {
                    const int nn = nt * 8;
                    sA2[(r + g)     * STRIDE_A2 + nn + 2 * tig]     = c[mb][nt][0];
                    sA2[(r + g)     * STRIDE_A2 + nn + 2 * tig + 1] = c[mb][nt][1];
                    sA2[(r + g + 8) * STRIDE_A2 + nn + 2 * tig]     = c[mb][nt][2];
                    sA2[(r + g + 8) * STRIDE_A2 + nn + 2 * tig + 1] = c[mb][nt][3];
                }
            }
        }
        __syncthreads();

        // ---- epilogue: gate + write ----
        for (int idx = tid; idx < NODE_TILE * 64; idx += THREADS) {
            const int z = idx >> 6;
            const int ww = idx & 63;
            const int zg = nb + z;
            if (zg >= n) continue;

            float s  = ALPHA_C * sA1[z * STRIDE_A1 + ww];
            float gg = ALPHA_C * sA1[z * STRIDE_A1 + 64 + ww];
            float v  = sA2[z * STRIDE_A2 + ww];
            float z0 = sA2[(64 + z)  * STRIDE_A2 + ww];
            float z1 = sA2[(128 + z) * STRIDE_A2 + ww];
            float z2 = sA2[(192 + z) * STRIDE_A2 + ww];

            float4 at4 = ((const float4*)sAttr)[z];
            const float a0v = at4.x;

            float sig_g = 1.0f / (1.0f + __expf(-gg));
            float silu  = s / (1.0f + __expf(-s));

            float o0 = ALPHA_C * (C011_C * at4.y * v + C101_C * a0v * z0);
            float o1 = ALPHA_C * (C011_C * at4.z * v + C101_C * a0v * z1);
            float o2 = ALPHA_C * (C011_C * at4.w * v + C101_C * a0v * z2);

            float* ob = out + (size_t)zg * (4 * MUL);
            ob[ww] = silu;
            ob[64 + 3 * ww + 0] = sig_g * o0;
            ob[64 + 3 * ww + 1] = sig_g * o1;
            ob[64 + 3 * ww + 2] = sig_g * o2;
        }
    }
}

extern "C" void kernel_launch(void* const* d_in, const int* in_sizes, int n_in,
                              void* d_out, int out_size)
{
    const float* feats = (const float*)d_in[0];
    const float* attrs = (const float*)d_in[1];
    const float* W1 = (const float*)d_in[2];
    const float* W2 = (const float*)d_in[3];
    const float* W3 = (const float*)d_in[4];
    const float* W4 = (const float*)d_in[5];
    float* out = (float*)d_out;

    const int n = in_sizes[0] / (4 * MUL);
    const int ntiles = (n + NODE_TILE - 1) / NODE_TILE;

    cudaFuncSetAttribute(embedding_kernel,
                         cudaFuncAttributeMaxDynamicSharedMemorySize, SMEM_BYTES);

    int grid = GRID_CTAS < ntiles ? GRID_CTAS : ntiles;
    embedding_kernel<<<grid, THREADS, SMEM_BYTES>>>(feats, attrs, W1, W2, W3, W4,
                                                    out, n, ntiles);
}